// round 5
// baseline (speedup 1.0000x reference)
#include <cuda_runtime.h>

#define NB 2
#define NC 128
#define NH 64
#define NW 64
#define NG 8
#define NPIX 4096
#define HP 78
#define PP (78*78)
#define NBORD 1988   // border pixels per padded plane: 2*7*78 + 2*64*7

// Channel-interleaved layouts:
//  Q: [(b*NG+g)*NPIX + pix]*4 + cq   (cq = channel quad, float4 each)
//  K/V: [(b*NG+g)*PP + off]*4 + cq   (off = padded-7 coords)
__device__ float4 g_Q[NB*NG*NPIX*4];
__device__ float4 g_K[NB*NG*PP*4];
__device__ float4 g_V[NB*NG*PP*4];

// Zero only the 7-wide halo of each padded plane (interior is overwritten by qkv).
__global__ __launch_bounds__(256) void zero_border_kernel() {
    int i = blockIdx.x * 256 + threadIdx.x;
    const int n = NB*NG*NBORD*4;
    if (i >= n) return;
    int cq = i & 3;
    int r = i >> 2;
    int bp = r % NBORD;
    int bg = r / NBORD;
    int off;
    if (bp < 546) {                       // top rows y=0..6
        off = (bp / 78)*HP + (bp % 78);
    } else if (bp < 1092) {               // bottom rows y=71..77
        int q = bp - 546;
        off = (71 + q / 78)*HP + (q % 78);
    } else if (bp < 1540) {               // left cols, y=7..70, x=0..6
        int q = bp - 1092;
        off = (7 + q / 7)*HP + (q % 7);
    } else {                              // right cols, x=71..77
        int q = bp - 1540;
        off = (7 + q / 7)*HP + 71 + (q % 7);
    }
    int idx = (bg*PP + off)*4 + cq;
    float4 z = make_float4(0.f, 0.f, 0.f, 0.f);
    g_K[idx] = z;
    g_V[idx] = z;
}

// One block: 64 pixels x 128 output channels for one of {Q,K,V} (blockIdx.z).
// Thread: 4 pixels (float4 input loads) x 8 outputs. 256 threads.
__global__ __launch_bounds__(256) void qkv_kernel(
    const float* __restrict__ fm,
    const float* __restrict__ wq,
    const float* __restrict__ wk,
    const float* __restrict__ wv)
{
    const int m = blockIdx.z;           // 0=Q, 1=K, 2=V
    const int b = blockIdx.y;
    const int pixbase = blockIdx.x * 64;
    const int tid = threadIdx.x;
    const int p4 = tid & 15;            // pixel quad 0..15
    const int og = tid >> 4;            // output octet 0..15

    const float* W = (m == 0) ? wq : (m == 1) ? wk : wv;
    const float* xin = fm + ((size_t)b*2*NC + (m == 0 ? NC : 0))*NPIX + pixbase + p4*4;
    const float* Wb = W + og*8*NC;

    float acc[8][4];
    #pragma unroll
    for (int k = 0; k < 8; k++)
        acc[k][0] = acc[k][1] = acc[k][2] = acc[k][3] = 0.f;

    #pragma unroll 2
    for (int c4 = 0; c4 < 32; c4++) {
        float4 xv[4];
        #pragma unroll
        for (int cc = 0; cc < 4; cc++)
            xv[cc] = *reinterpret_cast<const float4*>(xin + (size_t)(c4*4 + cc)*NPIX);
        #pragma unroll
        for (int k = 0; k < 8; k++) {
            float4 w4 = *reinterpret_cast<const float4*>(Wb + k*NC + c4*4);
            acc[k][0] += w4.x*xv[0].x + w4.y*xv[1].x + w4.z*xv[2].x + w4.w*xv[3].x;
            acc[k][1] += w4.x*xv[0].y + w4.y*xv[1].y + w4.z*xv[2].y + w4.w*xv[3].y;
            acc[k][2] += w4.x*xv[0].z + w4.y*xv[1].z + w4.z*xv[2].z + w4.w*xv[3].z;
            acc[k][3] += w4.x*xv[0].w + w4.y*xv[1].w + w4.z*xv[2].w + w4.w*xv[3].w;
        }
    }

    const int o0 = og * 8;
    const int g = o0 >> 4;
    const int cq0 = (o0 & 15) >> 2;     // 0 or 2
    #pragma unroll
    for (int pi = 0; pi < 4; pi++) {
        int pixel = pixbase + p4*4 + pi;
        float4 v0 = make_float4(acc[0][pi], acc[1][pi], acc[2][pi], acc[3][pi]);
        float4 v1 = make_float4(acc[4][pi], acc[5][pi], acc[6][pi], acc[7][pi]);
        if (m == 0) {
            int base = ((b*NG + g)*NPIX + pixel)*4;
            g_Q[base + cq0]     = v0;
            g_Q[base + cq0 + 1] = v1;
        } else {
            int y = pixel >> 6, x = pixel & 63;
            int off = (y + 7)*HP + (x + 7);
            float4* dst = (m == 1) ? g_K : g_V;
            int base = ((b*NG + g)*PP + off)*4;
            dst[base + cq0]     = v0;
            dst[base + cq0 + 1] = v1;
        }
    }
}

// 4 threads per pixel (one per channel quad). Warp = 8 consecutive x pixels x 4 cq
// -> fully consecutive 512B loads per tap. Logits distributed over the 4 lanes
// (owner: tap&3 == cq), dot reduction via width-4 butterfly shuffles.
__global__ __launch_bounds__(256) void attn_kernel(
    const float* __restrict__ rel_h,
    const float* __restrict__ rel_w,
    float* __restrict__ out)
{
    int t = blockIdx.x * 256 + threadIdx.x;
    const int cq = t & 3;
    const int p = t >> 2;                 // (b*NG+g)*NPIX + y*64 + x
    const int x = p & 63;
    const int y = (p >> 6) & 63;
    const int g = (p >> 12) & 7;
    const int b = p >> 15;
    const int bg = p >> 12;

    const float4 qv = g_Q[(size_t)p*4 + cq];
    const float4* __restrict__ Kb = g_K + (size_t)bg*PP*4;
    const float4* __restrict__ Vb = g_V + (size_t)bg*PP*4;

    // bias over full 16 channels via butterfly of 4-channel partials
    const float* rel = (g < 4) ? (rel_h + (g*16 + cq*4)*7)
                               : (rel_w + ((g - 4)*16 + cq*4)*7);
    float bias[7];
    #pragma unroll
    for (int i = 0; i < 7; i++) {
        float s = qv.x*rel[i] + qv.y*rel[7 + i] + qv.z*rel[14 + i] + qv.w*rel[21 + i];
        s += __shfl_xor_sync(0xffffffffu, s, 1);
        s += __shfl_xor_sync(0xffffffffu, s, 2);
        bias[i] = s;
    }
    const bool useI = (g < 4);

    float oa0 = 0.f, oa1 = 0.f, oa2 = 0.f, oa3 = 0.f;

    // ================= main 7x7 window =================
    {
        float lgq[13];
        float mx = -1e30f;
        #pragma unroll
        for (int tp = 0; tp < 49; tp++) {
            const int i = tp / 7, j = tp % 7;
            int off = (y + 4 + i)*HP + (x + 4 + j);
            float4 kv = Kb[off*4 + cq];
            float d = qv.x*kv.x + qv.y*kv.y + qv.z*kv.z + qv.w*kv.w;
            d += __shfl_xor_sync(0xffffffffu, d, 1);
            d += __shfl_xor_sync(0xffffffffu, d, 2);
            d += useI ? bias[i] : bias[j];
            if ((tp & 3) == cq) lgq[tp >> 2] = d;
            mx = fmaxf(mx, d);
        }
        float sp = 0.f;
        #pragma unroll
        for (int q = 0; q < 13; q++) {
            if (q < 12 || cq == 0) {
                float e = __expf(lgq[q] - mx);
                lgq[q] = e;
                sp += e;
            }
        }
        sp += __shfl_xor_sync(0xffffffffu, sp, 1);
        sp += __shfl_xor_sync(0xffffffffu, sp, 2);
        float inv = 1.0f / sp;
        #pragma unroll
        for (int q = 0; q < 13; q++) lgq[q] *= inv;

        #pragma unroll
        for (int tp = 0; tp < 49; tp++) {
            const int i = tp / 7, j = tp % 7;
            int off = (y + 4 + i)*HP + (x + 4 + j);
            float w = __shfl_sync(0xffffffffu, lgq[tp >> 2], tp & 3, 4);
            float4 vv = Vb[off*4 + cq];
            oa0 += w*vv.x; oa1 += w*vv.y; oa2 += w*vv.z; oa3 += w*vv.w;
        }
    }

    // ================= refine: row (15 taps along W) =================
    {
        float lgq[4];
        float mx = -1e30f;
        #pragma unroll
        for (int tp = 0; tp < 15; tp++) {
            int off = (y + 7)*HP + (x + tp);
            float4 kv = Kb[off*4 + cq];
            float d = qv.x*kv.x + qv.y*kv.y + qv.z*kv.z + qv.w*kv.w;
            d += __shfl_xor_sync(0xffffffffu, d, 1);
            d += __shfl_xor_sync(0xffffffffu, d, 2);
            if ((tp & 3) == cq) lgq[tp >> 2] = d;
            mx = fmaxf(mx, d);
        }
        float sp = 0.f;
        #pragma unroll
        for (int q = 0; q < 4; q++) {
            if (q < 3 || cq < 3) {
                float e = __expf(lgq[q] - mx);
                lgq[q] = e;
                sp += e;
            }
        }
        sp += __shfl_xor_sync(0xffffffffu, sp, 1);
        sp += __shfl_xor_sync(0xffffffffu, sp, 2);
        float inv = 1.0f / sp;
        #pragma unroll
        for (int q = 0; q < 4; q++) lgq[q] *= inv;

        #pragma unroll
        for (int tp = 0; tp < 15; tp++) {
            int off = (y + 7)*HP + (x + tp);
            float w = __shfl_sync(0xffffffffu, lgq[tp >> 2], tp & 3, 4);
            float4 vv = Vb[off*4 + cq];
            oa0 += w*vv.x; oa1 += w*vv.y; oa2 += w*vv.z; oa3 += w*vv.w;
        }
    }

    // ================= refine: col (15 taps along H) =================
    {
        float lgq[4];
        float mx = -1e30f;
        #pragma unroll
        for (int tp = 0; tp < 15; tp++) {
            int off = (y + tp)*HP + (x + 7);
            float4 kv = Kb[off*4 + cq];
            float d = qv.x*kv.x + qv.y*kv.y + qv.z*kv.z + qv.w*kv.w;
            d += __shfl_xor_sync(0xffffffffu, d, 1);
            d += __shfl_xor_sync(0xffffffffu, d, 2);
            if ((tp & 3) == cq) lgq[tp >> 2] = d;
            mx = fmaxf(mx, d);
        }
        float sp = 0.f;
        #pragma unroll
        for (int q = 0; q < 4; q++) {
            if (q < 3 || cq < 3) {
                float e = __expf(lgq[q] - mx);
                lgq[q] = e;
                sp += e;
            }
        }
        sp += __shfl_xor_sync(0xffffffffu, sp, 1);
        sp += __shfl_xor_sync(0xffffffffu, sp, 2);
        float inv = 1.0f / sp;
        #pragma unroll
        for (int q = 0; q < 4; q++) lgq[q] *= inv;

        #pragma unroll
        for (int tp = 0; tp < 15; tp++) {
            int off = (y + tp)*HP + (x + 7);
            float w = __shfl_sync(0xffffffffu, lgq[tp >> 2], tp & 3, 4);
            float4 vv = Vb[off*4 + cq];
            oa0 += w*vv.x; oa1 += w*vv.y; oa2 += w*vv.z; oa3 += w*vv.w;
        }
    }

    // out[b][g*16 + cq*4 + k][y][x]
    float* ob = out + ((size_t)b*NC + g*16 + cq*4)*NPIX + (y*NW + x);
    ob[0*NPIX] = oa0;
    ob[1*NPIX] = oa1;
    ob[2*NPIX] = oa2;
    ob[3*NPIX] = oa3;
}

extern "C" void kernel_launch(void* const* d_in, const int* in_sizes, int n_in,
                              void* d_out, int out_size) {
    const float* fm = (const float*)d_in[0];
    const float* wq = (const float*)d_in[1];
    const float* wk = (const float*)d_in[2];
    const float* wv = (const float*)d_in[3];
    const float* rh = (const float*)d_in[4];
    const float* rw = (const float*)d_in[5];
    float* out = (float*)d_out;

    const int nz = NB*NG*NBORD*4;
    zero_border_kernel<<<(nz + 255) / 256, 256>>>();

    dim3 grid(64, NB, 3);
    qkv_kernel<<<grid, 256>>>(fm, wq, wk, wv);

    attn_kernel<<<NB*NG*NPIX*4/256, 256>>>(rh, rw, out);
}

// round 6
// speedup vs baseline: 1.0782x; 1.0782x over previous
#include <cuda_runtime.h>

#define NB 2
#define NC 128
#define NH 64
#define NW 64
#define NG 8
#define NPIX 4096
#define HP 78
#define PP (78*78)
#define NBORD 1988   // border pixels per padded plane: 2*7*78 + 2*64*7
#define ZB 249       // ceil(NG*NBORD*4 / 256) border-zero blocks per (b, m)

// Plane-per-cq layouts (R4 style, shuffle-free attn):
//  Q: [(b*NG+g)*4 + cq]*NPIX + pix
//  K/V: [(b*NG+g)*4 + cq]*PP + off   (off = padded-7 coords)
__device__ float4 g_Q[NB*NG*4*NPIX];
__device__ float4 g_K[NB*NG*4*PP];
__device__ float4 g_V[NB*NG*4*PP];

// One kernel: blocks with bx<64 do the 1x1-conv GEMM; blocks with bx>=64 zero
// the 7-wide halo of the padded K/V planes (disjoint regions -> safe to fuse).
__global__ __launch_bounds__(256) void qkv_kernel(
    const float* __restrict__ fm,
    const float* __restrict__ wq,
    const float* __restrict__ wk,
    const float* __restrict__ wv)
{
    const int m = blockIdx.z;           // 0=Q, 1=K, 2=V
    const int b = blockIdx.y;
    const int bx = blockIdx.x;

    if (bx >= 64) {
        // ---- border zeroing (m==1 -> K, m==2 -> V, m==0 idle) ----
        if (m == 0) return;
        int i = (bx - 64)*256 + threadIdx.x;
        if (i >= NG*NBORD*4) return;
        int cq = i & 3;
        int r = i >> 2;
        int bp = r % NBORD;
        int gg = r / NBORD;
        int off;
        if (bp < 546) {                       // top rows y=0..6
            off = (bp / 78)*HP + (bp % 78);
        } else if (bp < 1092) {               // bottom rows y=71..77
            int q = bp - 546;
            off = (71 + q / 78)*HP + (q % 78);
        } else if (bp < 1540) {               // left cols, y=7..70, x=0..6
            int q = bp - 1092;
            off = (7 + q / 7)*HP + (q % 7);
        } else {                              // right cols, x=71..77
            int q = bp - 1540;
            off = (7 + q / 7)*HP + 71 + (q % 7);
        }
        int idx = ((b*NG + gg)*4 + cq)*PP + off;
        float4 z = make_float4(0.f, 0.f, 0.f, 0.f);
        if (m == 1) g_K[idx] = z; else g_V[idx] = z;
        return;
    }

    // ---- GEMM: 64 pixels x 128 out-channels. Thread: 4 pixels x 8 outputs ----
    const int pixbase = bx * 64;
    const int tid = threadIdx.x;
    const int p4 = tid & 15;            // pixel quad 0..15
    const int og = tid >> 4;            // output octet 0..15

    const float* W = (m == 0) ? wq : (m == 1) ? wk : wv;
    const float* xin = fm + ((size_t)b*2*NC + (m == 0 ? NC : 0))*NPIX + pixbase + p4*4;
    const float* Wb = W + og*8*NC;

    float acc[8][4];
    #pragma unroll
    for (int k = 0; k < 8; k++)
        acc[k][0] = acc[k][1] = acc[k][2] = acc[k][3] = 0.f;

    #pragma unroll 2
    for (int c4 = 0; c4 < 32; c4++) {
        float4 xv[4];
        #pragma unroll
        for (int cc = 0; cc < 4; cc++)
            xv[cc] = *reinterpret_cast<const float4*>(xin + (size_t)(c4*4 + cc)*NPIX);
        #pragma unroll
        for (int k = 0; k < 8; k++) {
            float4 w4 = *reinterpret_cast<const float4*>(Wb + k*NC + c4*4);
            acc[k][0] += w4.x*xv[0].x + w4.y*xv[1].x + w4.z*xv[2].x + w4.w*xv[3].x;
            acc[k][1] += w4.x*xv[0].y + w4.y*xv[1].y + w4.z*xv[2].y + w4.w*xv[3].y;
            acc[k][2] += w4.x*xv[0].z + w4.y*xv[1].z + w4.z*xv[2].z + w4.w*xv[3].z;
            acc[k][3] += w4.x*xv[0].w + w4.y*xv[1].w + w4.z*xv[2].w + w4.w*xv[3].w;
        }
    }

    const int o0 = og * 8;
    const int g = o0 >> 4;
    const int cq0 = (o0 & 15) >> 2;     // 0 or 2
    #pragma unroll
    for (int pi = 0; pi < 4; pi++) {
        int pixel = pixbase + p4*4 + pi;
        float4 v0 = make_float4(acc[0][pi], acc[1][pi], acc[2][pi], acc[3][pi]);
        float4 v1 = make_float4(acc[4][pi], acc[5][pi], acc[6][pi], acc[7][pi]);
        if (m == 0) {
            int base = ((b*NG + g)*4)*NPIX + pixel;
            g_Q[base + cq0*NPIX]       = v0;
            g_Q[base + (cq0 + 1)*NPIX] = v1;
        } else {
            int y = pixel >> 6, x = pixel & 63;
            int off = (y + 7)*HP + (x + 7);
            float4* dst = (m == 1) ? g_K : g_V;
            int base = ((b*NG + g)*4)*PP + off;
            dst[base + cq0*PP]       = v0;
            dst[base + (cq0 + 1)*PP] = v1;
        }
    }
}

// One thread per (b, g, y-pair, x): processes 2 vertically-adjacent pixels so
// the 7x7 window rows (8 shared) and col-refine rows (16 shared) are loaded
// once. Main window uses fused online raw-exp softmax (no logit array).
__global__ __launch_bounds__(256) void attn_kernel(
    const float* __restrict__ rel_h,
    const float* __restrict__ rel_w,
    float* __restrict__ out)
{
    int t = blockIdx.x * 256 + threadIdx.x;
    const int x  = t & 63;
    const int y2 = (t >> 6) & 31;
    const int g  = (t >> 11) & 7;
    const int b  = t >> 14;
    const int y0 = y2 * 2;
    const int bg = b*NG + g;

    const float4* __restrict__ Qp = g_Q + (size_t)bg*4*NPIX;
    const float4* __restrict__ Kp = g_K + (size_t)bg*4*PP;
    const float4* __restrict__ Vp = g_V + (size_t)bg*4*PP;

    float qa[2][16];
    #pragma unroll
    for (int py = 0; py < 2; py++) {
        int pix = (y0 + py)*NW + x;
        #pragma unroll
        for (int cq = 0; cq < 4; cq++) {
            float4 qv = Qp[cq*NPIX + pix];
            qa[py][cq*4+0] = qv.x; qa[py][cq*4+1] = qv.y;
            qa[py][cq*4+2] = qv.z; qa[py][cq*4+3] = qv.w;
        }
    }

    const float* rel = (g < 4) ? (rel_h + g*16*7) : (rel_w + (g - 4)*16*7);
    float bias[2][7];
    #pragma unroll
    for (int i = 0; i < 7; i++) {
        float s0 = 0.f, s1 = 0.f;
        #pragma unroll
        for (int c = 0; c < 16; c++) {
            float rv = rel[c*7 + i];
            s0 += qa[0][c] * rv;
            s1 += qa[1][c] * rv;
        }
        bias[0][i] = s0;
        bias[1][i] = s1;
    }
    const bool useI = (g < 4);

    float oa[2][16];
    #pragma unroll
    for (int py = 0; py < 2; py++)
        #pragma unroll
        for (int c = 0; c < 16; c++) oa[py][c] = 0.f;

    // ===== main 7x7 window: fused K+V pass, online raw-exp softmax =====
    {
        float s0 = 0.f, s1 = 0.f;
        #pragma unroll
        for (int rr = 0; rr < 8; rr++) {      // shared padded rows y0+4+rr
            #pragma unroll
            for (int j = 0; j < 7; j++) {
                int off = (y0 + 4 + rr)*HP + (x + 4 + j);
                float4 k0 = Kp[0*PP + off], k1 = Kp[1*PP + off];
                float4 k2 = Kp[2*PP + off], k3 = Kp[3*PP + off];
                float4 v0 = Vp[0*PP + off], v1 = Vp[1*PP + off];
                float4 v2 = Vp[2*PP + off], v3 = Vp[3*PP + off];
                if (rr < 7) {   // pixel 0: window row i = rr
                    float d = (useI ? bias[0][rr] : bias[0][j])
                        + qa[0][0]*k0.x + qa[0][1]*k0.y + qa[0][2]*k0.z + qa[0][3]*k0.w
                        + qa[0][4]*k1.x + qa[0][5]*k1.y + qa[0][6]*k1.z + qa[0][7]*k1.w
                        + qa[0][8]*k2.x + qa[0][9]*k2.y + qa[0][10]*k2.z + qa[0][11]*k2.w
                        + qa[0][12]*k3.x + qa[0][13]*k3.y + qa[0][14]*k3.z + qa[0][15]*k3.w;
                    float e = __expf(d);
                    s0 += e;
                    oa[0][0] += e*v0.x; oa[0][1] += e*v0.y; oa[0][2] += e*v0.z; oa[0][3] += e*v0.w;
                    oa[0][4] += e*v1.x; oa[0][5] += e*v1.y; oa[0][6] += e*v1.z; oa[0][7] += e*v1.w;
                    oa[0][8] += e*v2.x; oa[0][9] += e*v2.y; oa[0][10] += e*v2.z; oa[0][11] += e*v2.w;
                    oa[0][12] += e*v3.x; oa[0][13] += e*v3.y; oa[0][14] += e*v3.z; oa[0][15] += e*v3.w;
                }
                if (rr >= 1) {  // pixel 1: window row i = rr-1
                    float d = (useI ? bias[1][rr-1] : bias[1][j])
                        + qa[1][0]*k0.x + qa[1][1]*k0.y + qa[1][2]*k0.z + qa[1][3]*k0.w
                        + qa[1][4]*k1.x + qa[1][5]*k1.y + qa[1][6]*k1.z + qa[1][7]*k1.w
                        + qa[1][8]*k2.x + qa[1][9]*k2.y + qa[1][10]*k2.z + qa[1][11]*k2.w
                        + qa[1][12]*k3.x + qa[1][13]*k3.y + qa[1][14]*k3.z + qa[1][15]*k3.w;
                    float e = __expf(d);
                    s1 += e;
                    oa[1][0] += e*v0.x; oa[1][1] += e*v0.y; oa[1][2] += e*v0.z; oa[1][3] += e*v0.w;
                    oa[1][4] += e*v1.x; oa[1][5] += e*v1.y; oa[1][6] += e*v1.z; oa[1][7] += e*v1.w;
                    oa[1][8] += e*v2.x; oa[1][9] += e*v2.y; oa[1][10] += e*v2.z; oa[1][11] += e*v2.w;
                    oa[1][12] += e*v3.x; oa[1][13] += e*v3.y; oa[1][14] += e*v3.z; oa[1][15] += e*v3.w;
                }
            }
        }
        float inv0 = 1.0f / s0, inv1 = 1.0f / s1;
        #pragma unroll
        for (int c = 0; c < 16; c++) { oa[0][c] *= inv0; oa[1][c] *= inv1; }
    }

    // ===== refine row: per pixel, two-pass (no y sharing) =====
    #pragma unroll
    for (int py = 0; py < 2; py++) {
        const int row = (y0 + py + 7)*HP;
        float e[15];
        float ss = 0.f;
        #pragma unroll
        for (int tp = 0; tp < 15; tp++) {
            int off = row + x + tp;
            float4 k0 = Kp[0*PP + off], k1 = Kp[1*PP + off];
            float4 k2 = Kp[2*PP + off], k3 = Kp[3*PP + off];
            float d =
                  qa[py][0]*k0.x + qa[py][1]*k0.y + qa[py][2]*k0.z + qa[py][3]*k0.w
                + qa[py][4]*k1.x + qa[py][5]*k1.y + qa[py][6]*k1.z + qa[py][7]*k1.w
                + qa[py][8]*k2.x + qa[py][9]*k2.y + qa[py][10]*k2.z + qa[py][11]*k2.w
                + qa[py][12]*k3.x + qa[py][13]*k3.y + qa[py][14]*k3.z + qa[py][15]*k3.w;
            float ev = __expf(d);
            e[tp] = ev;
            ss += ev;
        }
        float inv = 1.0f / ss;
        #pragma unroll
        for (int tp = 0; tp < 15; tp++) {
            int off = row + x + tp;
            float w = e[tp] * inv;
            float4 v0 = Vp[0*PP + off], v1 = Vp[1*PP + off];
            float4 v2 = Vp[2*PP + off], v3 = Vp[3*PP + off];
            oa[py][0] += w*v0.x; oa[py][1] += w*v0.y; oa[py][2] += w*v0.z; oa[py][3] += w*v0.w;
            oa[py][4] += w*v1.x; oa[py][5] += w*v1.y; oa[py][6] += w*v1.z; oa[py][7] += w*v1.w;
            oa[py][8] += w*v2.x; oa[py][9] += w*v2.y; oa[py][10] += w*v2.z; oa[py][11] += w*v2.w;
            oa[py][12] += w*v3.x; oa[py][13] += w*v3.y; oa[py][14] += w*v3.z; oa[py][15] += w*v3.w;
        }
    }

    // ===== refine col: shared rows y0..y0+15, two-pass =====
    {
        float e0[15], e1[15];
        float s0 = 0.f, s1 = 0.f;
        #pragma unroll
        for (int rr = 0; rr < 16; rr++) {
            int off = (y0 + rr)*HP + (x + 7);
            float4 k0 = Kp[0*PP + off], k1 = Kp[1*PP + off];
            float4 k2 = Kp[2*PP + off], k3 = Kp[3*PP + off];
            if (rr < 15) {
                float d =
                      qa[0][0]*k0.x + qa[0][1]*k0.y + qa[0][2]*k0.z + qa[0][3]*k0.w
                    + qa[0][4]*k1.x + qa[0][5]*k1.y + qa[0][6]*k1.z + qa[0][7]*k1.w
                    + qa[0][8]*k2.x + qa[0][9]*k2.y + qa[0][10]*k2.z + qa[0][11]*k2.w
                    + qa[0][12]*k3.x + qa[0][13]*k3.y + qa[0][14]*k3.z + qa[0][15]*k3.w;
                float ev = __expf(d);
                e0[rr] = ev;
                s0 += ev;
            }
            if (rr >= 1) {
                float d =
                      qa[1][0]*k0.x + qa[1][1]*k0.y + qa[1][2]*k0.z + qa[1][3]*k0.w
                    + qa[1][4]*k1.x + qa[1][5]*k1.y + qa[1][6]*k1.z + qa[1][7]*k1.w
                    + qa[1][8]*k2.x + qa[1][9]*k2.y + qa[1][10]*k2.z + qa[1][11]*k2.w
                    + qa[1][12]*k3.x + qa[1][13]*k3.y + qa[1][14]*k3.z + qa[1][15]*k3.w;
                float ev = __expf(d);
                e1[rr-1] = ev;
                s1 += ev;
            }
        }
        float inv0 = 1.0f / s0, inv1 = 1.0f / s1;
        #pragma unroll
        for (int rr = 0; rr < 16; rr++) {
            int off = (y0 + rr)*HP + (x + 7);
            float4 v0 = Vp[0*PP + off], v1 = Vp[1*PP + off];
            float4 v2 = Vp[2*PP + off], v3 = Vp[3*PP + off];
            if (rr < 15) {
                float w = e0[rr] * inv0;
                oa[0][0] += w*v0.x; oa[0][1] += w*v0.y; oa[0][2] += w*v0.z; oa[0][3] += w*v0.w;
                oa[0][4] += w*v1.x; oa[0][5] += w*v1.y; oa[0][6] += w*v1.z; oa[0][7] += w*v1.w;
                oa[0][8] += w*v2.x; oa[0][9] += w*v2.y; oa[0][10] += w*v2.z; oa[0][11] += w*v2.w;
                oa[0][12] += w*v3.x; oa[0][13] += w*v3.y; oa[0][14] += w*v3.z; oa[0][15] += w*v3.w;
            }
            if (rr >= 1) {
                float w = e1[rr-1] * inv1;
                oa[1][0] += w*v0.x; oa[1][1] += w*v0.y; oa[1][2] += w*v0.z; oa[1][3] += w*v0.w;
                oa[1][4] += w*v1.x; oa[1][5] += w*v1.y; oa[1][6] += w*v1.z; oa[1][7] += w*v1.w;
                oa[1][8] += w*v2.x; oa[1][9] += w*v2.y; oa[1][10] += w*v2.z; oa[1][11] += w*v2.w;
                oa[1][12] += w*v3.x; oa[1][13] += w*v3.y; oa[1][14] += w*v3.z; oa[1][15] += w*v3.w;
            }
        }
    }

    // ===== store: out[b][g*16+c][y0+py][x] =====
    #pragma unroll
    for (int py = 0; py < 2; py++) {
        float* ob = out + ((size_t)b*NC + g*16)*NPIX + (y0 + py)*NW + x;
        #pragma unroll
        for (int c = 0; c < 16; c++) ob[c*NPIX] = oa[py][c];
    }
}

extern "C" void kernel_launch(void* const* d_in, const int* in_sizes, int n_in,
                              void* d_out, int out_size) {
    const float* fm = (const float*)d_in[0];
    const float* wq = (const float*)d_in[1];
    const float* wk = (const float*)d_in[2];
    const float* wv = (const float*)d_in[3];
    const float* rh = (const float*)d_in[4];
    const float* rw = (const float*)d_in[5];
    float* out = (float*)d_out;

    dim3 grid(64 + ZB, NB, 3);
    qkv_kernel<<<grid, 256>>>(fm, wq, wk, wv);

    attn_kernel<<<NB*NG*NW*32/256, 256>>>(rh, rw, out);
}